// round 1
// baseline (speedup 1.0000x reference)
#include <cuda_runtime.h>
#include <cstdint>

#define CIN_THREADS 512
// dynamic smem layout (floats):
//   xs  [32*64]      = 2048   (x tile, [m][d])
//   hvs [128*64]     = 8192   (running h vector, [n][d])
//   ws  [2][16*256]  = 8192   (double-buffered W chunk, [kk][h])
//   red [16]
#define SMEM_FLOATS (2048 + 8192 + 8192 + 16)
#define SMEM_BYTES  (SMEM_FLOATS * 4)

__device__ __forceinline__ unsigned long long pk2(float lo, float hi) {
    unsigned long long r;
    asm("mov.b64 %0, {%1, %2};" : "=l"(r) : "f"(lo), "f"(hi));
    return r;
}
__device__ __forceinline__ void up2(unsigned long long v, float& lo, float& hi) {
    asm("mov.b64 {%0, %1}, %2;" : "=f"(lo), "=f"(hi) : "l"(v));
}
__device__ __forceinline__ unsigned long long mul2(unsigned long long a, unsigned long long b) {
    unsigned long long r;
    asm("mul.rn.f32x2 %0, %1, %2;" : "=l"(r) : "l"(a), "l"(b));
    return r;
}
__device__ __forceinline__ unsigned long long fma2(unsigned long long a, unsigned long long b,
                                                   unsigned long long c) {
    unsigned long long r;
    asm("fma.rn.f32x2 %0, %1, %2, %3;" : "=l"(r) : "l"(a), "l"(b), "l"(c));
    return r;
}

// Mainloop for one CIN layer: acc[hi][pair] += (xs[m][d] * hv[n][d]) * W[k][h]
// k = m*(1<<NSHIFT) + n. W staged through double-buffered SMEM chunks of 16 rows.
template <int NSHIFT>
__device__ __forceinline__ void cin_mainloop(
    const float* __restrict__ Wg,
    const float* __restrict__ xs,
    const float* __restrict__ hvp,
    float* __restrict__ wsbase,   // 2 buffers of 4096 floats
    int tid, int d0, int h0,
    unsigned long long acc[8][2])
{
    constexpr int NMASK   = (1 << NSHIFT) - 1;
    constexpr int NCHUNKS = (32 << NSHIFT) >> 4;   // Ktot / 16

    // stage chunk 0
    reinterpret_cast<float4*>(wsbase)[tid]       = reinterpret_cast<const float4*>(Wg)[tid];
    reinterpret_cast<float4*>(wsbase)[tid + 512] = reinterpret_cast<const float4*>(Wg)[tid + 512];
    __syncthreads();

    for (int c = 0; c < NCHUNKS; ++c) {
        float4 nf0, nf1;
        const bool more = (c + 1 < NCHUNKS);
        if (more) {
            const float4* src = reinterpret_cast<const float4*>(Wg + (size_t)(c + 1) * 4096);
            nf0 = src[tid];
            nf1 = src[tid + 512];
        }
        const float* __restrict__ wsb = wsbase + (size_t)(c & 1) * 4096;
        const int kbase = c << 4;
        #pragma unroll
        for (int kk = 0; kk < 16; ++kk) {
            const int k = kbase + kk;
            const int m = k >> NSHIFT;
            const int n = k & NMASK;
            const float4 xm = *reinterpret_cast<const float4*>(xs  + m * 64 + d0);
            const float4 hn = *reinterpret_cast<const float4*>(hvp + n * 64 + d0);
            const unsigned long long p0 = mul2(pk2(xm.x, xm.y), pk2(hn.x, hn.y));
            const unsigned long long p1 = mul2(pk2(xm.z, xm.w), pk2(hn.z, hn.w));
            const float4 wa = *reinterpret_cast<const float4*>(wsb + kk * 256 + h0);
            const float4 wb = *reinterpret_cast<const float4*>(wsb + kk * 256 + h0 + 4);
            const float wv[8] = {wa.x, wa.y, wa.z, wa.w, wb.x, wb.y, wb.z, wb.w};
            #pragma unroll
            for (int hi = 0; hi < 8; ++hi) {
                const unsigned long long w2 = pk2(wv[hi], wv[hi]);
                acc[hi][0] = fma2(p0, w2, acc[hi][0]);
                acc[hi][1] = fma2(p1, w2, acc[hi][1]);
            }
        }
        __syncthreads();            // all reads of ws[c&1] done
        if (more) {
            reinterpret_cast<float4*>(wsbase + (size_t)((c + 1) & 1) * 4096)[tid]       = nf0;
            reinterpret_cast<float4*>(wsbase + (size_t)((c + 1) & 1) * 4096)[tid + 512] = nf1;
        }
        __syncthreads();            // next buffer visible
    }
}

__global__ __launch_bounds__(CIN_THREADS, 1)
void cin_kernel(const float* __restrict__ x,
                const float* __restrict__ W0, const float* __restrict__ b0,
                const float* __restrict__ W1, const float* __restrict__ b1,
                const float* __restrict__ W2, const float* __restrict__ b2,
                const float* __restrict__ fcW, const float* __restrict__ fcb,
                float* __restrict__ out)
{
    extern __shared__ float smem[];
    float* xs     = smem;                    // 2048
    float* hvs    = smem + 2048;             // 8192
    float* wsbase = smem + 2048 + 8192;      // 2 * 4096
    float* red    = smem + 2048 + 8192 + 8192;

    const int b   = blockIdx.x;
    const int tid = threadIdx.x;
    const int d0  = (tid & 15) << 2;   // this thread's 4 d-values
    const int h0  = (tid >> 4) << 3;   // this thread's 8 h-values

    // load x[b] : 32x64 floats
    reinterpret_cast<float4*>(xs)[tid] =
        reinterpret_cast<const float4*>(x + (size_t)b * 2048)[tid];
    __syncthreads();

    float fc_acc = 0.0f;

    const float* Wl[3] = {W0, W1, W2};
    const float* bl[3] = {b0, b1, b2};

    for (int layer = 0; layer < 3; ++layer) {
        unsigned long long acc[8][2];
        #pragma unroll
        for (int i = 0; i < 8; ++i) { acc[i][0] = 0ULL; acc[i][1] = 0ULL; }

        if (layer == 0)
            cin_mainloop<5>(Wl[0], xs, xs,  wsbase, tid, d0, h0, acc);
        else if (layer == 1)
            cin_mainloop<7>(Wl[1], xs, hvs, wsbase, tid, d0, h0, acc);
        else
            cin_mainloop<7>(Wl[2], xs, hvs, wsbase, tid, d0, h0, acc);

        // epilogue: bias + relu
        const float* __restrict__ bias = bl[layer];
        float yv[8][4];
        #pragma unroll
        for (int hi = 0; hi < 8; ++hi) {
            float v0, v1, v2, v3;
            up2(acc[hi][0], v0, v1);
            up2(acc[hi][1], v2, v3);
            const float bb = bias[h0 + hi];
            yv[hi][0] = fmaxf(v0 + bb, 0.0f);
            yv[hi][1] = fmaxf(v1 + bb, 0.0f);
            yv[hi][2] = fmaxf(v2 + bb, 0.0f);
            yv[hi][3] = fmaxf(v3 + bb, 0.0f);
        }

        if (layer < 2) {
            if (h0 < 128) {
                // first half -> x_cur -> fc contribution (fc_W rows layer*128 + h)
                #pragma unroll
                for (int hi = 0; hi < 8; ++hi)
                    fc_acc += fcW[layer * 128 + h0 + hi] *
                              (yv[hi][0] + yv[hi][1] + yv[hi][2] + yv[hi][3]);
            } else {
                // second half -> next h vector (safe: last mainloop barrier
                // ordered all hvs reads before these writes)
                #pragma unroll
                for (int hi = 0; hi < 8; ++hi)
                    *reinterpret_cast<float4*>(hvs + (h0 - 128 + hi) * 64 + d0) =
                        make_float4(yv[hi][0], yv[hi][1], yv[hi][2], yv[hi][3]);
            }
            __syncthreads();
        } else {
            // last layer: whole y feeds fc (fc_W rows 256 + h)
            #pragma unroll
            for (int hi = 0; hi < 8; ++hi)
                fc_acc += fcW[256 + h0 + hi] *
                          (yv[hi][0] + yv[hi][1] + yv[hi][2] + yv[hi][3]);
        }
    }

    // block reduction of fc partials
    #pragma unroll
    for (int off = 16; off > 0; off >>= 1)
        fc_acc += __shfl_xor_sync(0xffffffffu, fc_acc, off);
    if ((tid & 31) == 0) red[tid >> 5] = fc_acc;
    __syncthreads();
    if (tid == 0) {
        float s = 0.0f;
        #pragma unroll
        for (int i = 0; i < 16; ++i) s += red[i];
        out[b] = s + fcb[0];
    }
}

extern "C" void kernel_launch(void* const* d_in, const int* in_sizes, int n_in,
                              void* d_out, int out_size) {
    const float* x   = (const float*)d_in[0];
    const float* W0  = (const float*)d_in[1];
    const float* b0  = (const float*)d_in[2];
    const float* W1  = (const float*)d_in[3];
    const float* b1  = (const float*)d_in[4];
    const float* W2  = (const float*)d_in[5];
    const float* b2  = (const float*)d_in[6];
    const float* fcW = (const float*)d_in[7];
    const float* fcb = (const float*)d_in[8];
    float* out = (float*)d_out;

    cudaFuncSetAttribute(cin_kernel, cudaFuncAttributeMaxDynamicSharedMemorySize, SMEM_BYTES);
    cin_kernel<<<1024, CIN_THREADS, SMEM_BYTES>>>(x, W0, b0, W1, b1, W2, b2, fcW, fcb, out);
}

// round 2
// speedup vs baseline: 1.0013x; 1.0013x over previous
#include <cuda_runtime.h>
#include <cstdint>

#define CIN_THREADS 512
// dynamic smem layout (floats):
//   xs  [32*64]      = 2048   (x tile, [m][d])
//   hvs [128*64]     = 8192   (running h vector, [n][d])
//   ws  [2][16*256]  = 8192   (double-buffered W chunk, [kk][h])
//   red [16]
#define SMEM_FLOATS (2048 + 8192 + 8192 + 16)
#define SMEM_BYTES  (SMEM_FLOATS * 4)

__device__ __forceinline__ unsigned long long pk2(float lo, float hi) {
    unsigned long long r;
    asm("mov.b64 %0, {%1, %2};" : "=l"(r) : "f"(lo), "f"(hi));
    return r;
}
__device__ __forceinline__ void up2(unsigned long long v, float& lo, float& hi) {
    asm("mov.b64 {%0, %1}, %2;" : "=f"(lo), "=f"(hi) : "l"(v));
}
__device__ __forceinline__ unsigned long long mul2(unsigned long long a, unsigned long long b) {
    unsigned long long r;
    asm("mul.rn.f32x2 %0, %1, %2;" : "=l"(r) : "l"(a), "l"(b));
    return r;
}
__device__ __forceinline__ unsigned long long fma2(unsigned long long a, unsigned long long b,
                                                   unsigned long long c) {
    unsigned long long r;
    asm("fma.rn.f32x2 %0, %1, %2, %3;" : "=l"(r) : "l"(a), "l"(b), "l"(c));
    return r;
}

// Mainloop for one CIN layer: acc[hi][pair] += (xs[m][d] * hv[n][d]) * W[k][h]
// k = m*(1<<NSHIFT) + n. W staged through double-buffered SMEM chunks of 16 rows.
template <int NSHIFT>
__device__ __forceinline__ void cin_mainloop(
    const float* __restrict__ Wg,
    const float* __restrict__ xs,
    const float* __restrict__ hvp,
    float* __restrict__ wsbase,   // 2 buffers of 4096 floats
    int tid, int d0, int h0,
    unsigned long long acc[8][2])
{
    constexpr int NMASK   = (1 << NSHIFT) - 1;
    constexpr int NCHUNKS = (32 << NSHIFT) >> 4;   // Ktot / 16

    // stage chunk 0
    reinterpret_cast<float4*>(wsbase)[tid]       = reinterpret_cast<const float4*>(Wg)[tid];
    reinterpret_cast<float4*>(wsbase)[tid + 512] = reinterpret_cast<const float4*>(Wg)[tid + 512];
    __syncthreads();

    for (int c = 0; c < NCHUNKS; ++c) {
        float4 nf0, nf1;
        const bool more = (c + 1 < NCHUNKS);
        if (more) {
            const float4* src = reinterpret_cast<const float4*>(Wg + (size_t)(c + 1) * 4096);
            nf0 = src[tid];
            nf1 = src[tid + 512];
        }
        const float* __restrict__ wsb = wsbase + (size_t)(c & 1) * 4096;
        const int kbase = c << 4;
        #pragma unroll
        for (int kk = 0; kk < 16; ++kk) {
            const int k = kbase + kk;
            const int m = k >> NSHIFT;
            const int n = k & NMASK;
            const float4 xm = *reinterpret_cast<const float4*>(xs  + m * 64 + d0);
            const float4 hn = *reinterpret_cast<const float4*>(hvp + n * 64 + d0);
            const unsigned long long p0 = mul2(pk2(xm.x, xm.y), pk2(hn.x, hn.y));
            const unsigned long long p1 = mul2(pk2(xm.z, xm.w), pk2(hn.z, hn.w));
            const float4 wa = *reinterpret_cast<const float4*>(wsb + kk * 256 + h0);
            const float4 wb = *reinterpret_cast<const float4*>(wsb + kk * 256 + h0 + 4);
            const float wv[8] = {wa.x, wa.y, wa.z, wa.w, wb.x, wb.y, wb.z, wb.w};
            #pragma unroll
            for (int hi = 0; hi < 8; ++hi) {
                const unsigned long long w2 = pk2(wv[hi], wv[hi]);
                acc[hi][0] = fma2(p0, w2, acc[hi][0]);
                acc[hi][1] = fma2(p1, w2, acc[hi][1]);
            }
        }
        __syncthreads();            // all reads of ws[c&1] done
        if (more) {
            reinterpret_cast<float4*>(wsbase + (size_t)((c + 1) & 1) * 4096)[tid]       = nf0;
            reinterpret_cast<float4*>(wsbase + (size_t)((c + 1) & 1) * 4096)[tid + 512] = nf1;
        }
        __syncthreads();            // next buffer visible
    }
}

__global__ __launch_bounds__(CIN_THREADS, 1)
void cin_kernel(const float* __restrict__ x,
                const float* __restrict__ W0, const float* __restrict__ b0,
                const float* __restrict__ W1, const float* __restrict__ b1,
                const float* __restrict__ W2, const float* __restrict__ b2,
                const float* __restrict__ fcW, const float* __restrict__ fcb,
                float* __restrict__ out)
{
    extern __shared__ float smem[];
    float* xs     = smem;                    // 2048
    float* hvs    = smem + 2048;             // 8192
    float* wsbase = smem + 2048 + 8192;      // 2 * 4096
    float* red    = smem + 2048 + 8192 + 8192;

    const int b   = blockIdx.x;
    const int tid = threadIdx.x;
    const int d0  = (tid & 15) << 2;   // this thread's 4 d-values
    const int h0  = (tid >> 4) << 3;   // this thread's 8 h-values

    // load x[b] : 32x64 floats
    reinterpret_cast<float4*>(xs)[tid] =
        reinterpret_cast<const float4*>(x + (size_t)b * 2048)[tid];
    __syncthreads();

    float fc_acc = 0.0f;

    const float* Wl[3] = {W0, W1, W2};
    const float* bl[3] = {b0, b1, b2};

    for (int layer = 0; layer < 3; ++layer) {
        unsigned long long acc[8][2];
        #pragma unroll
        for (int i = 0; i < 8; ++i) { acc[i][0] = 0ULL; acc[i][1] = 0ULL; }

        if (layer == 0)
            cin_mainloop<5>(Wl[0], xs, xs,  wsbase, tid, d0, h0, acc);
        else if (layer == 1)
            cin_mainloop<7>(Wl[1], xs, hvs, wsbase, tid, d0, h0, acc);
        else
            cin_mainloop<7>(Wl[2], xs, hvs, wsbase, tid, d0, h0, acc);

        // epilogue: bias + relu
        const float* __restrict__ bias = bl[layer];
        float yv[8][4];
        #pragma unroll
        for (int hi = 0; hi < 8; ++hi) {
            float v0, v1, v2, v3;
            up2(acc[hi][0], v0, v1);
            up2(acc[hi][1], v2, v3);
            const float bb = bias[h0 + hi];
            yv[hi][0] = fmaxf(v0 + bb, 0.0f);
            yv[hi][1] = fmaxf(v1 + bb, 0.0f);
            yv[hi][2] = fmaxf(v2 + bb, 0.0f);
            yv[hi][3] = fmaxf(v3 + bb, 0.0f);
        }

        if (layer < 2) {
            if (h0 < 128) {
                // first half -> x_cur -> fc contribution (fc_W rows layer*128 + h)
                #pragma unroll
                for (int hi = 0; hi < 8; ++hi)
                    fc_acc += fcW[layer * 128 + h0 + hi] *
                              (yv[hi][0] + yv[hi][1] + yv[hi][2] + yv[hi][3]);
            } else {
                // second half -> next h vector (safe: last mainloop barrier
                // ordered all hvs reads before these writes)
                #pragma unroll
                for (int hi = 0; hi < 8; ++hi)
                    *reinterpret_cast<float4*>(hvs + (h0 - 128 + hi) * 64 + d0) =
                        make_float4(yv[hi][0], yv[hi][1], yv[hi][2], yv[hi][3]);
            }
            __syncthreads();
        } else {
            // last layer: whole y feeds fc (fc_W rows 256 + h)
            #pragma unroll
            for (int hi = 0; hi < 8; ++hi)
                fc_acc += fcW[256 + h0 + hi] *
                          (yv[hi][0] + yv[hi][1] + yv[hi][2] + yv[hi][3]);
        }
    }

    // block reduction of fc partials
    #pragma unroll
    for (int off = 16; off > 0; off >>= 1)
        fc_acc += __shfl_xor_sync(0xffffffffu, fc_acc, off);
    if ((tid & 31) == 0) red[tid >> 5] = fc_acc;
    __syncthreads();
    if (tid == 0) {
        float s = 0.0f;
        #pragma unroll
        for (int i = 0; i < 16; ++i) s += red[i];
        out[b] = s + fcb[0];
    }
}

extern "C" void kernel_launch(void* const* d_in, const int* in_sizes, int n_in,
                              void* d_out, int out_size) {
    const float* x   = (const float*)d_in[0];
    const float* W0  = (const float*)d_in[1];
    const float* b0  = (const float*)d_in[2];
    const float* W1  = (const float*)d_in[3];
    const float* b1  = (const float*)d_in[4];
    const float* W2  = (const float*)d_in[5];
    const float* b2  = (const float*)d_in[6];
    const float* fcW = (const float*)d_in[7];
    const float* fcb = (const float*)d_in[8];
    float* out = (float*)d_out;

    cudaFuncSetAttribute(cin_kernel, cudaFuncAttributeMaxDynamicSharedMemorySize, SMEM_BYTES);
    cin_kernel<<<1024, CIN_THREADS, SMEM_BYTES>>>(x, W0, b0, W1, b1, W2, b2, fcW, fcb, out);
}

// round 4
// speedup vs baseline: 2.4629x; 2.4598x over previous
#include <cuda_runtime.h>
#include <cuda_bf16.h>
#include <cstdint>

#define THREADS 512
#define NCHUNKS_TOT 288          // L0:32  L1:128  L2:128

// Pre-swizzled A images: per chunk 2 mtiles x (128 rows x 128B {32k hi|32k lo})
__device__ __align__(16) unsigned char g_Wimg[(size_t)NCHUNKS_TOT * 32768];

// ---- SMEM layout (bytes) ----
#define ABUF_OFF 0                 // 2 x 32768
#define BBUF_OFF 65536             // 2 x 16384
#define XS_OFF   98304             // 2 x 32 x 65 x 4  = 16640
#define HS_OFF   114944            // 2 x 128 x 65 x 4 = 66560
#define RED_OFF  181504            // 16 floats
#define SMEM_BYTES (RED_OFF + 256)

__device__ __forceinline__ uint32_t smem_u32(const void* p) {
    uint32_t a;
    asm("{ .reg .u64 t; cvta.to.shared.u64 t, %1; cvt.u32.u64 %0, t; }" : "=r"(a) : "l"(p));
    return a;
}
__device__ __forceinline__ uint32_t sw128(uint32_t o) { return o ^ ((o >> 3) & 0x70); }
__device__ __forceinline__ uint32_t pkbf(float a, float b) {
    __nv_bfloat16 ha = __float2bfloat16(a), hb = __float2bfloat16(b);
    return (uint32_t)__bfloat16_as_ushort(ha) | ((uint32_t)__bfloat16_as_ushort(hb) << 16);
}
__device__ __forceinline__ void cp16(uint32_t dst, const void* src) {
    asm volatile("cp.async.cg.shared.global [%0], [%1], 16;" :: "r"(dst), "l"(src) : "memory");
}
__device__ __forceinline__ void cp_commit() {
    asm volatile("cp.async.commit_group;" ::: "memory");
}
__device__ __forceinline__ void cp_wait0() {
    asm volatile("cp.async.wait_group 0;" ::: "memory");
}
__device__ __forceinline__ void ldsm4(uint32_t* r, uint32_t addr) {
    asm volatile("ldmatrix.sync.aligned.m8n8.x4.shared.b16 {%0,%1,%2,%3}, [%4];"
                 : "=r"(r[0]), "=r"(r[1]), "=r"(r[2]), "=r"(r[3]) : "r"(addr));
}
__device__ __forceinline__ void mma16816(float* c, const uint32_t* a, const uint32_t* b) {
    asm volatile("mma.sync.aligned.m16n8k16.row.col.f32.bf16.bf16.f32 "
                 "{%0,%1,%2,%3}, {%4,%5,%6,%7}, {%8,%9}, {%0,%1,%2,%3};"
                 : "+f"(c[0]), "+f"(c[1]), "+f"(c[2]), "+f"(c[3])
                 : "r"(a[0]), "r"(a[1]), "r"(a[2]), "r"(a[3]), "r"(b[0]), "r"(b[1]));
}

// ---------------- pre-pass: build split-bf16 swizzled W images ----------------
__global__ __launch_bounds__(THREADS) void prep_kernel(
    const float* __restrict__ W0, const float* __restrict__ W1, const float* __restrict__ W2)
{
    const int g = blockIdx.x;
    const float* W; int kbase;
    if (g < 32)       { W = W0; kbase = g * 32; }
    else if (g < 160) { W = W1; kbase = (g - 32) * 32; }
    else              { W = W2; kbase = (g - 160) * 32; }
    unsigned char* dst = g_Wimg + (size_t)g * 32768;
    #pragma unroll
    for (int i = 0; i < 8; ++i) {
        const int p    = threadIdx.x + i * 512;   // 0..4095 (pairs of k)
        const int tile = p >> 11;
        const int row  = (p >> 4) & 127;
        const int kp   = p & 15;
        const int k    = kbase + 2 * kp;
        const float w0 = W[(size_t)k * 256 + tile * 128 + row];
        const float w1 = W[(size_t)(k + 1) * 256 + tile * 128 + row];
        const __nv_bfloat16 h0 = __float2bfloat16(w0), h1 = __float2bfloat16(w1);
        const uint32_t hi = (uint32_t)__bfloat16_as_ushort(h0) |
                            ((uint32_t)__bfloat16_as_ushort(h1) << 16);
        const uint32_t lo = pkbf(w0 - __bfloat162float(h0), w1 - __bfloat162float(h1));
        const uint32_t tb   = tile * 16384;
        const uint32_t offh = row * 128 + 4 * kp;
        *(uint32_t*)(dst + tb + sw128(offh))      = hi;
        *(uint32_t*)(dst + tb + sw128(offh + 64)) = lo;
    }
}

// ---------------- main kernel ----------------
__global__ __launch_bounds__(THREADS, 1) void cin_mma_kernel(
    const float* __restrict__ x,
    const float* __restrict__ b0, const float* __restrict__ b1, const float* __restrict__ b2,
    const float* __restrict__ fcW, const float* __restrict__ fcb,
    float* __restrict__ out)
{
    extern __shared__ unsigned char smem[];
    const uint32_t sbase = smem_u32(smem);
    float* xs  = (float*)(smem + XS_OFF);
    float* hs  = (float*)(smem + HS_OFF);
    float* red = (float*)(smem + RED_OFF);

    const int tid = threadIdx.x, wid = tid >> 5, lane = tid & 31;
    const int B2 = blockIdx.x;
    const int mt = wid >> 1, nt = wid & 1;     // warp tile: M rows mt*32.., cols nt*64..

    // ldmatrix lane addressing constants
    const int arow = lane & 15, ab16 = (lane >> 4) * 16;              // A frags
    const int brl  = ((lane >> 4) << 3) + (lane & 7);                 // B frags
    const int bk16 = ((lane >> 3) & 1) * 16;

    // z-build mapping
    const int brow = tid >> 2;           // 0..127 : global n = batch*64 + d
    const int seg  = (tid & 3) * 8;      // k offset within chunk
    const int bb   = brow >> 6, bd = brow & 63;
    const float* xvb = xs + bb * 2080 + bd;
    const float* biasl[3] = {b0, b1, b2};

    // stage x pair into padded xs (stride 65)
    #pragma unroll
    for (int i = 0; i < 2; ++i) {
        const int idx = tid + i * 512;
        const float4 v = ((const float4*)(x + (size_t)B2 * 4096))[idx];
        const int f = idx * 4, bt = f >> 11, rem = f & 2047;
        float* dp = xs + bt * 2080 + (rem >> 6) * 65 + (rem & 63);
        dp[0] = v.x; dp[1] = v.y; dp[2] = v.z; dp[3] = v.w;
    }
    __syncthreads();

    float fc_acc = 0.0f;
    const int r0 = lane >> 2;

    for (int layer = 0; layer < 3; ++layer) {
        const int nch = (layer == 0) ? 32 : 128;
        const int g0  = (layer == 0) ? 0 : ((layer == 1) ? 32 : 160);
        const float* hvb = (layer == 0) ? (xs + bb * 2080 + bd) : (hs + bb * 8320 + bd);

        float acc[2][8][4];
        #pragma unroll
        for (int a = 0; a < 2; ++a)
            #pragma unroll
            for (int j = 0; j < 8; ++j)
                #pragma unroll
                for (int e = 0; e < 4; ++e) acc[a][j][e] = 0.0f;

        // --- stage(chunk cc -> buf) ---
        auto stage = [&](int cc, int buf) {
            const unsigned char* asrc = g_Wimg + (size_t)(g0 + cc) * 32768 + tid * 16;
            const uint32_t adst = sbase + ABUF_OFF + buf * 32768 + tid * 16;
            #pragma unroll
            for (int i = 0; i < 4; ++i) cp16(adst + i * 8192, asrc + i * 8192);
            cp_commit();

            const int m  = (layer == 0) ? cc : (cc >> 2);
            const int nb = (layer == 0) ? 0 : ((cc & 3) * 32);
            const float xv = xvb[m * 65];
            uint32_t hpk[4], lpk[4];
            #pragma unroll
            for (int q = 0; q < 4; ++q) {
                const float p0 = xv * hvb[(nb + seg + 2 * q) * 65];
                const float p1 = xv * hvb[(nb + seg + 2 * q + 1) * 65];
                const __nv_bfloat16 h0 = __float2bfloat16(p0), h1 = __float2bfloat16(p1);
                hpk[q] = (uint32_t)__bfloat16_as_ushort(h0) |
                         ((uint32_t)__bfloat16_as_ushort(h1) << 16);
                lpk[q] = pkbf(p0 - __bfloat162float(h0), p1 - __bfloat162float(h1));
            }
            unsigned char* bbs = smem + BBUF_OFF + buf * 16384;
            const uint32_t offh = brow * 128 + seg * 2;
            *(uint4*)(bbs + sw128(offh))      = make_uint4(hpk[0], hpk[1], hpk[2], hpk[3]);
            *(uint4*)(bbs + sw128(offh + 64)) = make_uint4(lpk[0], lpk[1], lpk[2], lpk[3]);
        };

        // --- compute(buf) : LDSM + 96 HMMA ---
        auto compute = [&](int buf) {
            const uint32_t ab = sbase + ABUF_OFF + buf * 32768 + (mt >> 2) * 16384;
            const uint32_t bbse = sbase + BBUF_OFF + buf * 16384;
            const int mrow0 = (mt & 3) * 32;
            #pragma unroll
            for (int ks = 0; ks < 2; ++ks) {
                uint32_t Ah[2][4], Al[2][4];
                #pragma unroll
                for (int mh = 0; mh < 2; ++mh) {
                    const uint32_t off = (uint32_t)(mrow0 + mh * 16 + arow) * 128 + 32 * ks + ab16;
                    ldsm4(Ah[mh], ab + sw128(off));
                    ldsm4(Al[mh], ab + sw128(off + 64));
                }
                #pragma unroll
                for (int jj = 0; jj < 4; ++jj) {
                    const uint32_t boff = (uint32_t)(nt * 64 + jj * 16 + brl) * 128 + 32 * ks + bk16;
                    uint32_t Bh[4], Bl[4];
                    ldsm4(Bh, bbse + sw128(boff));
                    ldsm4(Bl, bbse + sw128(boff + 64));
                    #pragma unroll
                    for (int mh = 0; mh < 2; ++mh) {
                        #pragma unroll
                        for (int jq = 0; jq < 2; ++jq) {
                            float* cc = acc[mh][2 * jj + jq];
                            mma16816(cc, Ah[mh], Bh + 2 * jq);
                            mma16816(cc, Ah[mh], Bl + 2 * jq);
                            mma16816(cc, Al[mh], Bh + 2 * jq);
                        }
                    }
                }
            }
        };

        stage(0, 0);
        cp_wait0();
        __syncthreads();

        for (int c = 0; c < nch; ++c) {
            const int cur = c & 1;
            const bool more = (c + 1 < nch);
            if (more) stage(c + 1, cur ^ 1);
            compute(cur);
            if (more) cp_wait0();
            __syncthreads();
        }

        // ---- epilogue ----
        const float* bl = biasl[layer];
        const int fcbase = (layer == 2) ? 256 : layer * 128;
        const bool do_fc = (layer == 2) || (mt < 4);
        float bias4[4], fw4[4];
        #pragma unroll
        for (int rr = 0; rr < 4; ++rr) {
            const int row = mt * 32 + rr * 8 + r0;   // rr = mh*2 + rh
            bias4[rr] = bl[row];
            fw4[rr] = do_fc ? fcW[fcbase + row] : 0.0f;
        }
        #pragma unroll
        for (int mh = 0; mh < 2; ++mh) {
            #pragma unroll
            for (int j = 0; j < 8; ++j) {
                #pragma unroll
                for (int e = 0; e < 4; ++e) {
                    const int rr = mh * 2 + (e >> 1);
                    const float v = fmaxf(acc[mh][j][e] + bias4[rr], 0.0f);
                    if (do_fc) {
                        fc_acc += fw4[rr] * v;
                    } else {
                        const int row = mt * 32 + mh * 16 + (e >> 1) * 8 + r0;
                        const int d   = 8 * j + 2 * (lane & 3) + (e & 1);
                        hs[nt * 8320 + (row - 128) * 65 + d] = v;
                    }
                }
            }
        }
        __syncthreads();
    }

    // final reduction: batch = nt = wid&1
    #pragma unroll
    for (int off = 16; off > 0; off >>= 1)
        fc_acc += __shfl_xor_sync(0xffffffffu, fc_acc, off);
    if (lane == 0) red[wid] = fc_acc;
    __syncthreads();
    if (tid == 0) {
        float s0 = 0.0f, s1 = 0.0f;
        #pragma unroll
        for (int w = 0; w < 16; ++w) {
            if (w & 1) s1 += red[w]; else s0 += red[w];
        }
        out[2 * B2]     = s0 + fcb[0];
        out[2 * B2 + 1] = s1 + fcb[0];
    }
}

extern "C" void kernel_launch(void* const* d_in, const int* in_sizes, int n_in,
                              void* d_out, int out_size) {
    const float* x   = (const float*)d_in[0];
    const float* W0  = (const float*)d_in[1];
    const float* b0  = (const float*)d_in[2];
    const float* W1  = (const float*)d_in[3];
    const float* b1  = (const float*)d_in[4];
    const float* W2  = (const float*)d_in[5];
    const float* b2  = (const float*)d_in[6];
    const float* fcW = (const float*)d_in[7];
    const float* fcb = (const float*)d_in[8];
    float* out = (float*)d_out;

    cudaFuncSetAttribute(cin_mma_kernel, cudaFuncAttributeMaxDynamicSharedMemorySize, SMEM_BYTES);
    prep_kernel<<<NCHUNKS_TOT, THREADS>>>(W0, W1, W2);
    cin_mma_kernel<<<512, THREADS, SMEM_BYTES>>>(x, b0, b1, b2, fcW, fcb, out);
}